// round 1
// baseline (speedup 1.0000x reference)
#include <cuda_runtime.h>
#include <cstdint>
#include <cstddef>

// Problem constants
#define L_DIM 1024
#define B_DIM 16
#define NIN   1024
#define NOUT  512
#define MDIM  (L_DIM * B_DIM)   // 16384
#define NGEMM (NOUT * 5)        // 2560
#define KGEMM NIN               // 1024

// Scratch (static device globals — no allocation)
__device__ float g_U[(size_t)MDIM * NGEMM];    // 160 MB: cols 0..2047 = (u1,u2,sig f1,sig f2) packed per n; 2048..2559 = sig(out)
__device__ float g_Wp[(size_t)KGEMM * NGEMM];  // 10 MB permuted weights

__device__ __forceinline__ float sigmoidf_fast(float x) {
    return 1.0f / (1.0f + __expf(-x));
}

// ---------------------------------------------------------------------------
// Weight permutation: column j'' of g_Wp:
//   j'' < 2048 : n = j''>>2, k = j''&3  -> source col n*5+k   (u1,u2,f1,f2)
//   j'' >=2048 : n = j''-2048           -> source col n*5+4   (output gate)
// ---------------------------------------------------------------------------
__global__ void permute_w_kernel(const float* __restrict__ w) {
    int idx = blockIdx.x * blockDim.x + threadIdx.x;   // over KGEMM*NGEMM
    int j2 = idx % NGEMM;
    int i  = idx / NGEMM;
    int j  = (j2 < 2048) ? ((j2 >> 2) * 5 + (j2 & 3)) : ((j2 - 2048) * 5 + 4);
    g_Wp[idx] = w[(size_t)i * NGEMM + j];
}

// ---------------------------------------------------------------------------
// TF32 mma.sync GEMM: C[16384,2560] = X[16384,1024] @ Wp[1024,2560]
// Tiles: BM=128, BN=128, BK=16, 256 threads (8 warps, 2x4), warp tile 64x32.
// Fused epilogue: sigmoid(+bias) on f1/f2/out planes, raw u1/u2; write g_U.
// ---------------------------------------------------------------------------
#define BM 128
#define BN 128
#define BK 16
#define AS_STRIDE 20    // conflict-free pad (bank = 4*gid+tig, all distinct)
#define BS_STRIDE 136   // conflict-free pad (bank = 8*tig+gid, all distinct)
#define NTHREADS 256

__device__ __forceinline__ unsigned smem_u32(const void* p) {
    return (unsigned)__cvta_generic_to_shared(p);
}
__device__ __forceinline__ void cp_async16(unsigned dst, const void* src) {
    asm volatile("cp.async.cg.shared.global [%0], [%1], 16;\n" :: "r"(dst), "l"(src));
}
__device__ __forceinline__ void cp_commit() { asm volatile("cp.async.commit_group;\n"); }
__device__ __forceinline__ void cp_wait0()  { asm volatile("cp.async.wait_group 0;\n"); }

__device__ __forceinline__ uint32_t f2tf32(float f) {
    uint32_t r; asm("cvt.rna.tf32.f32 %0, %1;" : "=r"(r) : "f"(f)); return r;
}

__device__ __forceinline__ void mma_tf32(float4& d, const uint32_t a[4], const uint32_t b[2]) {
    asm volatile(
        "mma.sync.aligned.m16n8k8.row.col.f32.tf32.tf32.f32 "
        "{%0,%1,%2,%3}, {%4,%5,%6,%7}, {%8,%9}, {%0,%1,%2,%3};"
        : "+f"(d.x), "+f"(d.y), "+f"(d.z), "+f"(d.w)
        : "r"(a[0]), "r"(a[1]), "r"(a[2]), "r"(a[3]), "r"(b[0]), "r"(b[1]));
}

__device__ __forceinline__ void store_elem(int row, int col, float v,
                                           const float* __restrict__ bias) {
    if (col < 2048) {
        int kk = col & 3;
        if (kk >= 2) {
            // forget gates: bias[k*NOUT + n], k = kk (2 or 3), n = col>>2
            v = sigmoidf_fast(v + __ldg(&bias[(kk << 9) + (col >> 2)]));
        }
    } else {
        // output gate: bias[4*NOUT + n]
        v = sigmoidf_fast(v + __ldg(&bias[2048 + (col - 2048)]));
    }
    g_U[(size_t)row * NGEMM + col] = v;
}

__global__ void __launch_bounds__(NTHREADS)
gemm_kernel(const float* __restrict__ x, const float* __restrict__ bias) {
    __shared__ float sm[2][BM * AS_STRIDE + BK * BS_STRIDE];

    const int tid  = threadIdx.x;
    const int warp = tid >> 5, lanei = tid & 31;
    const int gid  = lanei >> 2, tig = lanei & 3;   // group id / thread-in-group
    const int wm   = warp >> 2, wn = warp & 3;      // 2 x 4 warp grid
    const int m0   = blockIdx.y * BM;
    const int n0   = blockIdx.x * BN;

    float4 acc[4][4];
#pragma unroll
    for (int i = 0; i < 4; i++)
#pragma unroll
        for (int j = 0; j < 4; j++) acc[i][j] = make_float4(0.f, 0.f, 0.f, 0.f);

    auto load_tile = [&](int kt, int buf) {
        float* As = sm[buf];
        float* Bs = sm[buf] + BM * AS_STRIDE;
        const int k0 = kt * BK;
        // A: 128 rows x 16 cols = 512 float4 -> 2 per thread
#pragma unroll
        for (int i = 0; i < 2; i++) {
            int lin = i * NTHREADS + tid;
            int row = lin >> 2, c4 = lin & 3;
            const float* src = x + (size_t)(m0 + row) * KGEMM + k0 + c4 * 4;
            cp_async16(smem_u32(&As[row * AS_STRIDE + c4 * 4]), src);
        }
        // B: 16 rows x 128 cols = 512 float4 -> 2 per thread
#pragma unroll
        for (int i = 0; i < 2; i++) {
            int lin = i * NTHREADS + tid;
            int row = lin >> 5, c4 = lin & 31;
            const float* src = g_Wp + (size_t)(k0 + row) * NGEMM + n0 + c4 * 4;
            cp_async16(smem_u32(&Bs[row * BS_STRIDE + c4 * 4]), src);
        }
        cp_commit();
    };

    load_tile(0, 0);
    const int KT = KGEMM / BK;  // 64
    for (int kt = 0; kt < KT; ++kt) {
        int buf = kt & 1;
        cp_wait0();
        __syncthreads();
        if (kt + 1 < KT) load_tile(kt + 1, buf ^ 1);

        const float* As = sm[buf];
        const float* Bs = sm[buf] + BM * AS_STRIDE;
#pragma unroll
        for (int kk = 0; kk < BK; kk += 8) {
            uint32_t af[4][4];
#pragma unroll
            for (int im = 0; im < 4; im++) {
                int r0 = wm * 64 + im * 16 + gid;
                af[im][0] = f2tf32(As[r0 * AS_STRIDE + kk + tig]);
                af[im][1] = f2tf32(As[(r0 + 8) * AS_STRIDE + kk + tig]);
                af[im][2] = f2tf32(As[r0 * AS_STRIDE + kk + tig + 4]);
                af[im][3] = f2tf32(As[(r0 + 8) * AS_STRIDE + kk + tig + 4]);
            }
            uint32_t bf[4][2];
#pragma unroll
            for (int jn = 0; jn < 4; jn++) {
                int c0 = wn * 32 + jn * 8 + gid;
                bf[jn][0] = f2tf32(Bs[(kk + tig) * BS_STRIDE + c0]);
                bf[jn][1] = f2tf32(Bs[(kk + tig + 4) * BS_STRIDE + c0]);
            }
#pragma unroll
            for (int im = 0; im < 4; im++)
#pragma unroll
                for (int jn = 0; jn < 4; jn++)
                    mma_tf32(acc[im][jn], af[im], bf[jn]);
        }
        __syncthreads();
    }

    // Epilogue: transform + store
#pragma unroll
    for (int im = 0; im < 4; im++) {
#pragma unroll
        for (int jn = 0; jn < 4; jn++) {
            int col = n0 + wn * 32 + jn * 8 + tig * 2;
            int row = m0 + wm * 64 + im * 16 + gid;
            store_elem(row,     col,     acc[im][jn].x, bias);
            store_elem(row,     col + 1, acc[im][jn].y, bias);
            store_elem(row + 8, col,     acc[im][jn].z, bias);
            store_elem(row + 8, col + 1, acc[im][jn].w, bias);
        }
    }
}

// ---------------------------------------------------------------------------
// Sequential scan: 8192 lanes (b, n), 1024 steps each.
//   c1_t = c1*f1 + u1 ;  c2_t = c2*f2 + (eps + c1_prev)*u2
//   gcs  = tanh(sig_out * (c1*rho0 + c2*rho1))
// ---------------------------------------------------------------------------
__global__ void __launch_bounds__(128)
scan_kernel(const float* __restrict__ bias_eps, const float* __restrict__ bias_final,
            float* __restrict__ out) {
    int lane = blockIdx.x * blockDim.x + threadIdx.x;  // 0..8191
    int n = lane & (NOUT - 1);
    int b = lane >> 9;

    float eps  = sigmoidf_fast(__ldg(&bias_eps[n]));
    float rho0 = 2.0f * sigmoidf_fast(__ldg(&bias_final[2 * n]));
    float rho1 = 2.0f * sigmoidf_fast(__ldg(&bias_final[2 * n + 1]));

    float c1 = 0.0f, c2 = 0.0f;

    // row m = l*16 + b ; packed float4 at float index m*2560 + 4n ; og at m*2560 + 2048 + n
    const float4* qp  = reinterpret_cast<const float4*>(g_U) + (size_t)b * 640 + n;
    const float*  ogp = g_U + (size_t)b * 2560 + 2048 + n;
    float*        gp  = out + lane;

#pragma unroll 4
    for (int l = 0; l < L_DIM; ++l) {
        float4 q  = __ldg(qp);    // (u1, u2, sig_f1, sig_f2)
        float  og = __ldg(ogp);
        float c1n = fmaf(c1, q.z, q.x);
        float c2n = fmaf(c2, q.w, (eps + c1) * q.y);
        c1 = c1n; c2 = c2n;
        float t = og * (c1 * rho0 + c2 * rho1);
        float r;
        asm("tanh.approx.f32 %0, %1;" : "=f"(r) : "f"(t));
        *gp = r;
        qp  += 16 * 640;    // next l: m += 16
        ogp += 16 * 2560;
        gp  += B_DIM * NOUT;
    }
    // finals after gcs block
    const size_t GCS = (size_t)L_DIM * B_DIM * NOUT;
    out[GCS + lane]        = c1;
    out[GCS + 8192 + lane] = c2;
}

// ---------------------------------------------------------------------------
extern "C" void kernel_launch(void* const* d_in, const int* in_sizes, int n_in,
                              void* d_out, int out_size) {
    (void)in_sizes; (void)n_in; (void)out_size;
    const float* x          = (const float*)d_in[0];
    const float* weight     = (const float*)d_in[1];
    const float* bias       = (const float*)d_in[2];
    const float* bias_eps   = (const float*)d_in[3];
    const float* bias_final = (const float*)d_in[4];
    float* out = (float*)d_out;

    permute_w_kernel<<<(KGEMM * NGEMM) / 256, 256>>>(weight);

    dim3 grid(NGEMM / BN, MDIM / BM);  // (20, 128)
    gemm_kernel<<<grid, NTHREADS>>>(x, bias);

    scan_kernel<<<64, 128>>>(bias_eps, bias_final, out);
}

// round 3
// speedup vs baseline: 1.1219x; 1.1219x over previous
#include <cuda_runtime.h>
#include <cstdint>
#include <cstddef>

// ---------------- problem constants ----------------
#define L_DIM 1024
#define B_DIM 16
#define NIN   1024
#define NOUT  512
#define MDIM  16384            // L*B
#define NGEMM 2560             // NOUT*5
#define KGEMM 1024

// ---------------- GEMM tiling ----------------
#define BM 128
#define BN 256
#define KSTAGE 32
#define NSTAGES 4
#define KT (KGEMM / KSTAGE)                 // 32
#define A_BYTES (BM * KSTAGE * 4)           // 16384
#define B_BYTES (BN * KSTAGE * 4)           // 32768
#define STAGE_BYTES (A_BYTES + B_BYTES)     // 49152
#define SMEM_DYN (NSTAGES * STAGE_BYTES)    // 196608
#define NTHREADS 256

// ---------------- scratch (static, no allocation) ----------------
// g_U: 160 MB packed activations. cols 0..2047 = (u1,u2,sigf1,sigf2) per n; 2048..2559 = sig(out)
__device__ float g_U [(size_t)MDIM * NGEMM];
// g_Xa: X in A-fragment-major layout [M/16][K/8][32 lanes][4], tf32-rounded (64 MB)
__device__ float g_Xa[(size_t)MDIM * KGEMM];
// g_Wb: W permuted into B-fragment-major layout [N/8][K/16][32 lanes][4], tf32-rounded (10 MB)
__device__ float g_Wb[(size_t)NGEMM * KGEMM];

__device__ __forceinline__ float sigmoidf_fast(float x) {
    return 1.0f / (1.0f + __expf(-x));
}
__device__ __forceinline__ float tf32r(float f) {
    uint32_t r; asm("cvt.rna.tf32.f32 %0, %1;" : "=r"(r) : "f"(f));
    return __uint_as_float(r);
}
__device__ __forceinline__ uint32_t smem_u32(const void* p) {
    return (uint32_t)__cvta_generic_to_shared(p);
}
__device__ __forceinline__ void cp_async16(uint32_t dst, const float* src) {
    asm volatile("cp.async.cg.shared.global [%0], [%1], 16;\n" :: "r"(dst), "l"(src));
}

// mma m16n8k8 tf32: a = 4 regs (pre-rounded fp32 bits), b = 2 regs
__device__ __forceinline__ void mma_tf32(float4& d, uint4 a, uint32_t b0, uint32_t b1) {
    asm volatile(
        "mma.sync.aligned.m16n8k8.row.col.f32.tf32.tf32.f32 "
        "{%0,%1,%2,%3}, {%4,%5,%6,%7}, {%8,%9}, {%0,%1,%2,%3};"
        : "+f"(d.x), "+f"(d.y), "+f"(d.z), "+f"(d.w)
        : "r"(a.x), "r"(a.y), "r"(a.z), "r"(a.w), "r"(b0), "r"(b1));
}

// ---------------------------------------------------------------------------
// preround_frag: x[16384,1024] -> g_Xa fragment-major, tf32-rounded.
// Block = one (r16, 128-col) tile: loads 16x128 floats coalesced, re-emits as
// 16 fragment chunks of 512B (lane-major), stores coalesced stg.128.
// Fragment (m16n8k8 A): lane l -> g=l>>2, t=l&3; vals (g,t),(g+8,t),(g,t+4),(g+8,t+4)
// ---------------------------------------------------------------------------
__global__ void __launch_bounds__(256)
preround_frag(const float* __restrict__ x) {
    __shared__ float sm[16][132];   // padded: bank(4g+8k8l+tg) all distinct per warp
    const int tid = threadIdx.x;
    const int r16  = blockIdx.x >> 3;    // 0..1023
    const int kblk = blockIdx.x & 7;     // 0..7 (128 cols each)

#pragma unroll
    for (int i = 0; i < 2; i++) {
        int t = i * 256 + tid;           // 0..511 float4s
        int row = t >> 5, c4 = t & 31;
        float4 v = *(const float4*)(x + (size_t)(r16 * 16 + row) * KGEMM + kblk * 128 + c4 * 4);
        sm[row][c4 * 4 + 0] = v.x; sm[row][c4 * 4 + 1] = v.y;
        sm[row][c4 * 4 + 2] = v.z; sm[row][c4 * 4 + 3] = v.w;
    }
    __syncthreads();

#pragma unroll
    for (int i = 0; i < 2; i++) {
        int t = i * 256 + tid;           // 0..511 -> (k8l 0..15, lane)
        int k8l = t >> 5, lane = t & 31;
        int g = lane >> 2, tg = lane & 3;
        int c = k8l * 8 + tg;
        float4 o;
        o.x = tf32r(sm[g][c]);
        o.y = tf32r(sm[g + 8][c]);
        o.z = tf32r(sm[g][c + 4]);
        o.w = tf32r(sm[g + 8][c + 4]);
        size_t chunk = (size_t)r16 * 128 + kblk * 16 + k8l;
        *(float4*)(g_Xa + chunk * 128 + lane * 4) = o;
    }
}

// ---------------------------------------------------------------------------
// permw_frag: w[1024,2560] -> g_Wb fragment-major permuted, tf32-rounded.
// Permuted col j2: j2<2048: n=j2>>2,kk=j2&3 -> src col n*5+kk ; else out gate n*5+4
// Fragment (m16n8k8 B): lane l -> g=l>>2 (col), tg=l&3 (k); chunk (n8,k16) holds
// [b0(k16*16+tg), b1(+4), b0(+8), b1(+12)] for col n8*8+g.
// ---------------------------------------------------------------------------
__global__ void __launch_bounds__(256)
permw_frag(const float* __restrict__ w) {
    int t = blockIdx.x * 256 + threadIdx.x;   // over 320*64*32
    int lane = t & 31;
    int chunk = t >> 5;
    int k16 = chunk & 63, n8 = chunk >> 6;
    int g = lane >> 2, tg = lane & 3;
    int j2 = n8 * 8 + g;
    int j  = (j2 < 2048) ? ((j2 >> 2) * 5 + (j2 & 3)) : ((j2 - 2048) * 5 + 4);
    int k  = k16 * 16 + tg;
    float4 o;
    o.x = tf32r(w[(size_t)(k)      * NGEMM + j]);
    o.y = tf32r(w[(size_t)(k + 4)  * NGEMM + j]);
    o.z = tf32r(w[(size_t)(k + 8)  * NGEMM + j]);
    o.w = tf32r(w[(size_t)(k + 12) * NGEMM + j]);
    *(float4*)(g_Wb + (size_t)t * 4) = o;
}

// ---------------------------------------------------------------------------
// TF32 mma.sync GEMM: C[16384,2560] = Xa @ Wb^T. 128x256 CTA tile, 8 warps 2x4,
// warp tile 64x64 (4 im x 8 jn). Fragment-major smem: every frag = 1 LDS.128.
// Fused sigmoid epilogue -> g_U (float2 stores).
// ---------------------------------------------------------------------------
__global__ void __launch_bounds__(NTHREADS, 1)
gemm_kernel(const float* __restrict__ bias) {
    extern __shared__ char smraw[];
    const uint32_t sbase = smem_u32(smraw);

    const int tid = threadIdx.x;
    const int wid = tid >> 5, lane = tid & 31;
    const int gid = lane >> 2, tig = lane & 3;
    const int wm = wid >> 2, wn = wid & 3;       // 2 x 4 warps
    const int m0 = blockIdx.y * BM;
    const int n0 = blockIdx.x * BN;

    float4 acc[4][8];
#pragma unroll
    for (int i = 0; i < 4; i++)
#pragma unroll
        for (int j = 0; j < 8; j++) acc[i][j] = make_float4(0.f, 0.f, 0.f, 0.f);

    auto load_stage = [&](int s) {
        uint32_t sb = sbase + (uint32_t)(s & (NSTAGES - 1)) * STAGE_BYTES;
#pragma unroll
        for (int i = 0; i < 12; i++) {
            int t = i * NTHREADS + tid;           // 0..3071
            if (t < 1024) {                       // A: chunks (r16l 0..7, k8l 0..3)
                int chunk = t >> 5, ln = t & 31;
                int r16l = chunk >> 2, k8l = chunk & 3;
                const float* src = g_Xa +
                    ((size_t)((m0 >> 4) + r16l) * 128 + (s * 4 + k8l)) * 128 + ln * 4;
                cp_async16(sb + t * 16, src);
            } else {                              // B: chunks (n8l 0..31, k16l 0..1)
                int j = t - 1024;
                int chunk = j >> 5, ln = j & 31;
                int n8l = chunk >> 1, k16l = chunk & 1;
                const float* src = g_Wb +
                    ((size_t)((n0 >> 3) + n8l) * 64 + (s * 2 + k16l)) * 128 + ln * 4;
                cp_async16(sb + A_BYTES + j * 16, src);
            }
        }
        asm volatile("cp.async.commit_group;");
    };

    load_stage(0); load_stage(1); load_stage(2);

    for (int s = 0; s < KT; ++s) {
        if (s <= KT - 3)      asm volatile("cp.async.wait_group 2;");
        else if (s == KT - 2) asm volatile("cp.async.wait_group 1;");
        else                  asm volatile("cp.async.wait_group 0;");
        __syncthreads();
        if (s + 3 < KT) load_stage(s + 3);

        const char* As = smraw + (size_t)(s & (NSTAGES - 1)) * STAGE_BYTES;
        const char* Bs = As + A_BYTES;

#pragma unroll
        for (int k16 = 0; k16 < 2; k16++) {
            uint4 a[4][2];
#pragma unroll
            for (int im = 0; im < 4; im++)
#pragma unroll
                for (int k8 = 0; k8 < 2; k8++)
                    a[im][k8] = *(const uint4*)(As +
                        (((wm * 4 + im) * 4 + k16 * 2 + k8) * 32 + lane) * 16);
#pragma unroll
            for (int jn = 0; jn < 8; jn++) {
                uint4 b = *(const uint4*)(Bs +
                    (((wn * 8 + jn) * 2 + k16) * 32 + lane) * 16);
#pragma unroll
                for (int im = 0; im < 4; im++) {
                    mma_tf32(acc[im][jn], a[im][0], b.x, b.y);
                    mma_tf32(acc[im][jn], a[im][1], b.z, b.w);
                }
            }
        }
        __syncthreads();
    }

    // ---- epilogue: transform + float2 stores ----
#pragma unroll
    for (int im = 0; im < 4; im++) {
        const int row = m0 + wm * 64 + im * 16 + gid;
        float* r0p = g_U + (size_t)row * NGEMM;
        float* r1p = g_U + (size_t)(row + 8) * NGEMM;
#pragma unroll
        for (int jn = 0; jn < 8; jn++) {
            const int col = n0 + wn * 64 + jn * 8 + tig * 2;
            float4 c = acc[im][jn];
            if (col >= 2048) {
                float b0 = __ldg(&bias[col]);
                float b1 = __ldg(&bias[col + 1]);
                c.x = sigmoidf_fast(c.x + b0); c.y = sigmoidf_fast(c.y + b1);
                c.z = sigmoidf_fast(c.z + b0); c.w = sigmoidf_fast(c.w + b1);
            } else if (col & 2) {   // kk = 2,3 -> forget gates
                int n = col >> 2;
                float b0 = __ldg(&bias[1024 + n]);   // k=2 plane
                float b1 = __ldg(&bias[1536 + n]);   // k=3 plane
                c.x = sigmoidf_fast(c.x + b0); c.y = sigmoidf_fast(c.y + b1);
                c.z = sigmoidf_fast(c.z + b0); c.w = sigmoidf_fast(c.w + b1);
            }
            *(float2*)(r0p + col) = make_float2(c.x, c.y);
            *(float2*)(r1p + col) = make_float2(c.z, c.w);
        }
    }
}

// ---------------------------------------------------------------------------
// Sequential scan: 8192 lanes, 1024 steps.
// ---------------------------------------------------------------------------
__global__ void __launch_bounds__(64)
scan_kernel(const float* __restrict__ bias_eps, const float* __restrict__ bias_final,
            float* __restrict__ out) {
    int lane = blockIdx.x * blockDim.x + threadIdx.x;   // 0..8191
    int n = lane & (NOUT - 1);
    int b = lane >> 9;

    float eps  = sigmoidf_fast(__ldg(&bias_eps[n]));
    float rho0 = 2.0f * sigmoidf_fast(__ldg(&bias_final[2 * n]));
    float rho1 = 2.0f * sigmoidf_fast(__ldg(&bias_final[2 * n + 1]));

    float c1 = 0.0f, c2 = 0.0f;

    const float4* qp  = reinterpret_cast<const float4*>(g_U) + (size_t)b * 640 + n;
    const float*  ogp = g_U + (size_t)b * 2560 + 2048 + n;
    float*        gp  = out + lane;

#pragma unroll 4
    for (int l = 0; l < L_DIM; ++l) {
        float4 q  = __ldg(qp);     // (u1, u2, sig_f1, sig_f2)
        float  og = __ldg(ogp);
        float c1n = fmaf(c1, q.z, q.x);
        float c2n = fmaf(c2, q.w, (eps + c1) * q.y);
        c1 = c1n; c2 = c2n;
        float t = og * (c1 * rho0 + c2 * rho1);
        float r;
        asm("tanh.approx.f32 %0, %1;" : "=f"(r) : "f"(t));
        *gp = r;
        qp  += 16 * 640;
        ogp += 16 * 2560;
        gp  += B_DIM * NOUT;
    }
    const size_t GCS = (size_t)L_DIM * B_DIM * NOUT;
    out[GCS + lane]        = c1;
    out[GCS + 8192 + lane] = c2;
}

// ---------------------------------------------------------------------------
extern "C" void kernel_launch(void* const* d_in, const int* in_sizes, int n_in,
                              void* d_out, int out_size) {
    (void)in_sizes; (void)n_in; (void)out_size;
    const float* x          = (const float*)d_in[0];
    const float* weight     = (const float*)d_in[1];
    const float* bias       = (const float*)d_in[2];
    const float* bias_eps   = (const float*)d_in[3];
    const float* bias_final = (const float*)d_in[4];
    float* out = (float*)d_out;

    cudaFuncSetAttribute(gemm_kernel, cudaFuncAttributeMaxDynamicSharedMemorySize, SMEM_DYN);

    preround_frag<<<MDIM / 16 * (KGEMM / 128), 256>>>(x);      // 8192 blocks
    permw_frag<<<(NGEMM / 8) * (KGEMM / 16) * 32 / 256, 256>>>(weight);  // 2560 blocks

    dim3 grid(NGEMM / BN, MDIM / BM);   // (10, 128)
    gemm_kernel<<<grid, NTHREADS, SMEM_DYN>>>(bias);

    scan_kernel<<<128, 64>>>(bias_eps, bias_final, out);
}

// round 4
// speedup vs baseline: 1.5530x; 1.3843x over previous
#include <cuda_runtime.h>
#include <cstdint>
#include <cstddef>

// ---------------- problem constants ----------------
#define L_DIM 1024
#define B_DIM 16
#define NIN   1024
#define NOUT  512
#define MDIM  16384            // L*B
#define NGEMM 2560             // NOUT*5
#define KGEMM 1024

// ---------------- GEMM tiling ----------------
#define BM 128
#define BN 256
#define KSTAGE 32
#define NSTAGES 4
#define KT (KGEMM / KSTAGE)                 // 32
#define A_BYTES (BM * KSTAGE * 4)           // 16384
#define B_BYTES (BN * KSTAGE * 4)           // 32768
#define STAGE_BYTES (A_BYTES + B_BYTES)     // 49152
#define SMEM_DYN (NSTAGES * STAGE_BYTES)    // 196608
#define NTHREADS 256

// ---------------- scan chunking ----------------
#define NCH   16
#define CLEN  (L_DIM / NCH)                 // 64
#define NLANE 8192                          // B*NOUT

// ---------------- scratch (static, no allocation) ----------------
__device__ float g_U [(size_t)MDIM * NGEMM];   // 160 MB packed activations
__device__ float g_Xa[(size_t)MDIM * KGEMM];   // 64 MB A-fragment-major tf32 X
__device__ float g_Wb[(size_t)NGEMM * KGEMM];  // 10 MB B-fragment-major tf32 W
__device__ float g_coef[NCH * 5 * NLANE];      // per-chunk transfer coefficients
__device__ float g_init[NCH * 2 * NLANE];      // per-chunk initial carries

__device__ __forceinline__ float sigmoidf_fast(float x) {
    return 1.0f / (1.0f + __expf(-x));
}
__device__ __forceinline__ float tf32r(float f) {
    uint32_t r; asm("cvt.rna.tf32.f32 %0, %1;" : "=r"(r) : "f"(f));
    return __uint_as_float(r);
}
__device__ __forceinline__ uint32_t smem_u32(const void* p) {
    return (uint32_t)__cvta_generic_to_shared(p);
}
__device__ __forceinline__ void cp_async16(uint32_t dst, const float* src) {
    asm volatile("cp.async.cg.shared.global [%0], [%1], 16;\n" :: "r"(dst), "l"(src));
}
__device__ __forceinline__ void mma_tf32(float4& d, uint4 a, uint32_t b0, uint32_t b1) {
    asm volatile(
        "mma.sync.aligned.m16n8k8.row.col.f32.tf32.tf32.f32 "
        "{%0,%1,%2,%3}, {%4,%5,%6,%7}, {%8,%9}, {%0,%1,%2,%3};"
        : "+f"(d.x), "+f"(d.y), "+f"(d.z), "+f"(d.w)
        : "r"(a.x), "r"(a.y), "r"(a.z), "r"(a.w), "r"(b0), "r"(b1));
}

// ---------------------------------------------------------------------------
// preround_frag: x -> g_Xa (A-fragment-major, tf32-rounded)
// ---------------------------------------------------------------------------
__global__ void __launch_bounds__(256)
preround_frag(const float* __restrict__ x) {
    __shared__ float sm[16][132];
    const int tid = threadIdx.x;
    const int r16  = blockIdx.x >> 3;
    const int kblk = blockIdx.x & 7;

#pragma unroll
    for (int i = 0; i < 2; i++) {
        int t = i * 256 + tid;
        int row = t >> 5, c4 = t & 31;
        float4 v = *(const float4*)(x + (size_t)(r16 * 16 + row) * KGEMM + kblk * 128 + c4 * 4);
        sm[row][c4 * 4 + 0] = v.x; sm[row][c4 * 4 + 1] = v.y;
        sm[row][c4 * 4 + 2] = v.z; sm[row][c4 * 4 + 3] = v.w;
    }
    __syncthreads();

#pragma unroll
    for (int i = 0; i < 2; i++) {
        int t = i * 256 + tid;
        int k8l = t >> 5, lane = t & 31;
        int g = lane >> 2, tg = lane & 3;
        int c = k8l * 8 + tg;
        float4 o;
        o.x = tf32r(sm[g][c]);
        o.y = tf32r(sm[g + 8][c]);
        o.z = tf32r(sm[g][c + 4]);
        o.w = tf32r(sm[g + 8][c + 4]);
        size_t chunk = (size_t)r16 * 128 + kblk * 16 + k8l;
        *(float4*)(g_Xa + chunk * 128 + lane * 4) = o;
    }
}

// ---------------------------------------------------------------------------
// permw_frag: w -> g_Wb (B-fragment-major permuted, tf32-rounded)
// ---------------------------------------------------------------------------
__global__ void __launch_bounds__(256)
permw_frag(const float* __restrict__ w) {
    int t = blockIdx.x * 256 + threadIdx.x;
    int lane = t & 31;
    int chunk = t >> 5;
    int k16 = chunk & 63, n8 = chunk >> 6;
    int g = lane >> 2, tg = lane & 3;
    int j2 = n8 * 8 + g;
    int j  = (j2 < 2048) ? ((j2 >> 2) * 5 + (j2 & 3)) : ((j2 - 2048) * 5 + 4);
    int k  = k16 * 16 + tg;
    float4 o;
    o.x = tf32r(w[(size_t)(k)      * NGEMM + j]);
    o.y = tf32r(w[(size_t)(k + 4)  * NGEMM + j]);
    o.z = tf32r(w[(size_t)(k + 8)  * NGEMM + j]);
    o.w = tf32r(w[(size_t)(k + 12) * NGEMM + j]);
    *(float4*)(g_Wb + (size_t)t * 4) = o;
}

// ---------------------------------------------------------------------------
// TF32 mma.sync GEMM with fused sigmoid epilogue -> g_U
// ---------------------------------------------------------------------------
__global__ void __launch_bounds__(NTHREADS, 1)
gemm_kernel(const float* __restrict__ bias) {
    extern __shared__ char smraw[];
    const uint32_t sbase = smem_u32(smraw);

    const int tid = threadIdx.x;
    const int wid = tid >> 5, lane = tid & 31;
    const int gid = lane >> 2, tig = lane & 3;
    const int wm = wid >> 2, wn = wid & 3;
    const int m0 = blockIdx.y * BM;
    const int n0 = blockIdx.x * BN;

    float4 acc[4][8];
#pragma unroll
    for (int i = 0; i < 4; i++)
#pragma unroll
        for (int j = 0; j < 8; j++) acc[i][j] = make_float4(0.f, 0.f, 0.f, 0.f);

    auto load_stage = [&](int s) {
        uint32_t sb = sbase + (uint32_t)(s & (NSTAGES - 1)) * STAGE_BYTES;
#pragma unroll
        for (int i = 0; i < 12; i++) {
            int t = i * NTHREADS + tid;
            if (t < 1024) {
                int chunk = t >> 5, ln = t & 31;
                int r16l = chunk >> 2, k8l = chunk & 3;
                const float* src = g_Xa +
                    ((size_t)((m0 >> 4) + r16l) * 128 + (s * 4 + k8l)) * 128 + ln * 4;
                cp_async16(sb + t * 16, src);
            } else {
                int j = t - 1024;
                int chunk = j >> 5, ln = j & 31;
                int n8l = chunk >> 1, k16l = chunk & 1;
                const float* src = g_Wb +
                    ((size_t)((n0 >> 3) + n8l) * 64 + (s * 2 + k16l)) * 128 + ln * 4;
                cp_async16(sb + A_BYTES + j * 16, src);
            }
        }
        asm volatile("cp.async.commit_group;");
    };

    load_stage(0); load_stage(1); load_stage(2);

    for (int s = 0; s < KT; ++s) {
        if (s <= KT - 3)      asm volatile("cp.async.wait_group 2;");
        else if (s == KT - 2) asm volatile("cp.async.wait_group 1;");
        else                  asm volatile("cp.async.wait_group 0;");
        __syncthreads();
        if (s + 3 < KT) load_stage(s + 3);

        const char* As = smraw + (size_t)(s & (NSTAGES - 1)) * STAGE_BYTES;
        const char* Bs = As + A_BYTES;

#pragma unroll
        for (int k16 = 0; k16 < 2; k16++) {
            uint4 a[4][2];
#pragma unroll
            for (int im = 0; im < 4; im++)
#pragma unroll
                for (int k8 = 0; k8 < 2; k8++)
                    a[im][k8] = *(const uint4*)(As +
                        (((wm * 4 + im) * 4 + k16 * 2 + k8) * 32 + lane) * 16);
#pragma unroll
            for (int jn = 0; jn < 8; jn++) {
                uint4 b = *(const uint4*)(Bs +
                    (((wn * 8 + jn) * 2 + k16) * 32 + lane) * 16);
#pragma unroll
                for (int im = 0; im < 4; im++) {
                    mma_tf32(acc[im][jn], a[im][0], b.x, b.y);
                    mma_tf32(acc[im][jn], a[im][1], b.z, b.w);
                }
            }
        }
        // no bottom sync: buffer (s)&3 is only rewritten by load of s+4, which
        // happens after the top __syncthreads of iteration s+1.
    }

    // ---- epilogue: transform + float2 stores ----
#pragma unroll
    for (int im = 0; im < 4; im++) {
        const int row = m0 + wm * 64 + im * 16 + gid;
        float* r0p = g_U + (size_t)row * NGEMM;
        float* r1p = g_U + (size_t)(row + 8) * NGEMM;
#pragma unroll
        for (int jn = 0; jn < 8; jn++) {
            const int col = n0 + wn * 64 + jn * 8 + tig * 2;
            float4 c = acc[im][jn];
            if (col >= 2048) {
                float b0 = __ldg(&bias[col]);
                float b1 = __ldg(&bias[col + 1]);
                c.x = sigmoidf_fast(c.x + b0); c.y = sigmoidf_fast(c.y + b1);
                c.z = sigmoidf_fast(c.z + b0); c.w = sigmoidf_fast(c.w + b1);
            } else if (col & 2) {
                int n = col >> 2;
                float b0 = __ldg(&bias[1024 + n]);
                float b1 = __ldg(&bias[1536 + n]);
                c.x = sigmoidf_fast(c.x + b0); c.y = sigmoidf_fast(c.y + b1);
                c.z = sigmoidf_fast(c.z + b0); c.w = sigmoidf_fast(c.w + b1);
            }
            *(float2*)(r0p + col) = make_float2(c.x, c.y);
            *(float2*)(r1p + col) = make_float2(c.z, c.w);
        }
    }
}

// ---------------------------------------------------------------------------
// Scan pass 1: per-(lane, chunk) transfer coefficients.
//   c1(t) = a1*c1_0 + b1 ;  c2(t) = P*c2_0 + Q*c1_0 + R
// ---------------------------------------------------------------------------
__global__ void __launch_bounds__(256)
scan_pass1(const float* __restrict__ bias_eps) {
    int lane = blockIdx.x * 256 + threadIdx.x;   // 0..8191
    int ch   = blockIdx.y;                       // 0..15
    int n = lane & (NOUT - 1);
    int b = lane >> 9;

    float eps = sigmoidf_fast(__ldg(&bias_eps[n]));

    float a1 = 1.f, b1 = 0.f, P = 1.f, Q = 0.f, R = 0.f;

    const float4* qp = reinterpret_cast<const float4*>(g_U) +
                       (size_t)(ch * CLEN * 16 + b) * 640 + n;

#pragma unroll 4
    for (int l = 0; l < CLEN; ++l) {
        float4 q = __ldg(qp);    // (u1, u2, sig_f1, sig_f2)
        // uses (a1,b1) at t-1 first
        Q = fmaf(Q, q.w, a1 * q.y);
        R = fmaf(R, q.w, (eps + b1) * q.y);
        P = P * q.w;
        b1 = fmaf(b1, q.z, q.x);
        a1 = a1 * q.z;
        qp += 16 * 640;
    }
    g_coef[(ch * 5 + 0) * NLANE + lane] = a1;
    g_coef[(ch * 5 + 1) * NLANE + lane] = b1;
    g_coef[(ch * 5 + 2) * NLANE + lane] = P;
    g_coef[(ch * 5 + 3) * NLANE + lane] = Q;
    g_coef[(ch * 5 + 4) * NLANE + lane] = R;
}

// ---------------------------------------------------------------------------
// Combine: chain 16 chunks per lane; emit per-chunk initial carries + finals.
// ---------------------------------------------------------------------------
__global__ void __launch_bounds__(256)
scan_combine(float* __restrict__ out) {
    int lane = blockIdx.x * 256 + threadIdx.x;   // 0..8191
    float c1 = 0.f, c2 = 0.f;
#pragma unroll
    for (int ch = 0; ch < NCH; ++ch) {
        g_init[(ch * 2 + 0) * NLANE + lane] = c1;
        g_init[(ch * 2 + 1) * NLANE + lane] = c2;
        float a1 = g_coef[(ch * 5 + 0) * NLANE + lane];
        float b1 = g_coef[(ch * 5 + 1) * NLANE + lane];
        float P  = g_coef[(ch * 5 + 2) * NLANE + lane];
        float Q  = g_coef[(ch * 5 + 3) * NLANE + lane];
        float R  = g_coef[(ch * 5 + 4) * NLANE + lane];
        float c2n = fmaf(P, c2, fmaf(Q, c1, R));
        c1 = fmaf(a1, c1, b1);
        c2 = c2n;
    }
    const size_t GCS = (size_t)L_DIM * B_DIM * NOUT;
    out[GCS + lane]        = c1;
    out[GCS + 8192 + lane] = c2;
}

// ---------------------------------------------------------------------------
// Scan pass 2: replay each chunk from its carry; write gcs.
// ---------------------------------------------------------------------------
__global__ void __launch_bounds__(256)
scan_pass2(const float* __restrict__ bias_eps, const float* __restrict__ bias_final,
           float* __restrict__ out) {
    int lane = blockIdx.x * 256 + threadIdx.x;   // 0..8191
    int ch   = blockIdx.y;
    int n = lane & (NOUT - 1);
    int b = lane >> 9;

    float eps  = sigmoidf_fast(__ldg(&bias_eps[n]));
    float rho0 = 2.0f * sigmoidf_fast(__ldg(&bias_final[2 * n]));
    float rho1 = 2.0f * sigmoidf_fast(__ldg(&bias_final[2 * n + 1]));

    float c1 = g_init[(ch * 2 + 0) * NLANE + lane];
    float c2 = g_init[(ch * 2 + 1) * NLANE + lane];

    const float4* qp  = reinterpret_cast<const float4*>(g_U) +
                        (size_t)(ch * CLEN * 16 + b) * 640 + n;
    const float*  ogp = g_U + (size_t)(ch * CLEN * 16 + b) * 2560 + 2048 + n;
    float*        gp  = out + (size_t)ch * CLEN * NLANE + lane;

#pragma unroll 4
    for (int l = 0; l < CLEN; ++l) {
        float4 q  = __ldg(qp);
        float  og = __ldg(ogp);
        float c1n = fmaf(c1, q.z, q.x);
        float c2n = fmaf(c2, q.w, (eps + c1) * q.y);
        c1 = c1n; c2 = c2n;
        float t = og * (c1 * rho0 + c2 * rho1);
        float r;
        asm("tanh.approx.f32 %0, %1;" : "=f"(r) : "f"(t));
        *gp = r;
        qp  += 16 * 640;
        ogp += 16 * 2560;
        gp  += NLANE;
    }
}

// ---------------------------------------------------------------------------
extern "C" void kernel_launch(void* const* d_in, const int* in_sizes, int n_in,
                              void* d_out, int out_size) {
    (void)in_sizes; (void)n_in; (void)out_size;
    const float* x          = (const float*)d_in[0];
    const float* weight     = (const float*)d_in[1];
    const float* bias       = (const float*)d_in[2];
    const float* bias_eps   = (const float*)d_in[3];
    const float* bias_final = (const float*)d_in[4];
    float* out = (float*)d_out;

    cudaFuncSetAttribute(gemm_kernel, cudaFuncAttributeMaxDynamicSharedMemorySize, SMEM_DYN);

    preround_frag<<<MDIM / 16 * (KGEMM / 128), 256>>>(x);
    permw_frag<<<(NGEMM / 8) * (KGEMM / 16) * 32 / 256, 256>>>(weight);

    dim3 grid(NGEMM / BN, MDIM / BM);   // (10, 128)
    gemm_kernel<<<grid, NTHREADS, SMEM_DYN>>>(bias);

    dim3 sgrid(NLANE / 256, NCH);
    scan_pass1<<<sgrid, 256>>>(bias_eps);
    scan_combine<<<NLANE / 256, 256>>>(out);
    scan_pass2<<<sgrid, 256>>>(bias_eps, bias_final, out);
}

// round 5
// speedup vs baseline: 1.6245x; 1.0461x over previous
#include <cuda_runtime.h>
#include <cstdint>
#include <cstddef>

// ---------------- problem constants ----------------
#define L_DIM 1024
#define B_DIM 16
#define NIN   1024
#define NOUT  512
#define MDIM  16384            // L*B
#define NGEMM 2560             // NOUT*5
#define KGEMM 1024

// ---------------- GEMM tiling ----------------
#define BM 128
#define BN 256
#define KSTAGE 32
#define NSTAGES 4
#define KT (KGEMM / KSTAGE)                 // 32
#define A_BYTES (BM * KSTAGE * 4)           // 16384
#define B_BYTES (BN * KSTAGE * 4)           // 32768
#define STAGE_BYTES (A_BYTES + B_BYTES)     // 49152
#define SMEM_DYN (NSTAGES * STAGE_BYTES)    // 196608
#define NTHREADS 512

// ---------------- scan chunking ----------------
#define NCH   16
#define CLEN  (L_DIM / NCH)                 // 64
#define NLANE 8192                          // B*NOUT

// ---------------- scratch (static, no allocation) ----------------
__device__ float g_U [(size_t)MDIM * NGEMM];   // 160 MB packed activations
__device__ float g_Xa[(size_t)MDIM * KGEMM];   // 64 MB A-fragment-major tf32 X
__device__ float g_Wb[(size_t)NGEMM * KGEMM];  // 10 MB B-fragment-major tf32 W
__device__ float g_coef[NCH * 5 * NLANE];      // per-chunk transfer coefficients
__device__ float g_init[NCH * 2 * NLANE];      // per-chunk initial carries

__device__ __forceinline__ float sigmoidf_fast(float x) {
    return 1.0f / (1.0f + __expf(-x));
}
__device__ __forceinline__ float tf32r(float f) {
    uint32_t r; asm("cvt.rna.tf32.f32 %0, %1;" : "=r"(r) : "f"(f));
    return __uint_as_float(r);
}
__device__ __forceinline__ uint32_t smem_u32(const void* p) {
    return (uint32_t)__cvta_generic_to_shared(p);
}
__device__ __forceinline__ void cp_async16(uint32_t dst, const float* src) {
    asm volatile("cp.async.cg.shared.global [%0], [%1], 16;\n" :: "r"(dst), "l"(src));
}
__device__ __forceinline__ void mma_tf32(float4& d, uint4 a, uint32_t b0, uint32_t b1) {
    asm volatile(
        "mma.sync.aligned.m16n8k8.row.col.f32.tf32.tf32.f32 "
        "{%0,%1,%2,%3}, {%4,%5,%6,%7}, {%8,%9}, {%0,%1,%2,%3};"
        : "+f"(d.x), "+f"(d.y), "+f"(d.z), "+f"(d.w)
        : "r"(a.x), "r"(a.y), "r"(a.z), "r"(a.w), "r"(b0), "r"(b1));
}

// ---------------------------------------------------------------------------
// preround_frag: x -> g_Xa (A-fragment-major, tf32-rounded)
// ---------------------------------------------------------------------------
__global__ void __launch_bounds__(256)
preround_frag(const float* __restrict__ x) {
    __shared__ float sm[16][132];
    const int tid = threadIdx.x;
    const int r16  = blockIdx.x >> 3;
    const int kblk = blockIdx.x & 7;

#pragma unroll
    for (int i = 0; i < 2; i++) {
        int t = i * 256 + tid;
        int row = t >> 5, c4 = t & 31;
        float4 v = *(const float4*)(x + (size_t)(r16 * 16 + row) * KGEMM + kblk * 128 + c4 * 4);
        sm[row][c4 * 4 + 0] = v.x; sm[row][c4 * 4 + 1] = v.y;
        sm[row][c4 * 4 + 2] = v.z; sm[row][c4 * 4 + 3] = v.w;
    }
    __syncthreads();

#pragma unroll
    for (int i = 0; i < 2; i++) {
        int t = i * 256 + tid;
        int k8l = t >> 5, lane = t & 31;
        int g = lane >> 2, tg = lane & 3;
        int c = k8l * 8 + tg;
        float4 o;
        o.x = tf32r(sm[g][c]);
        o.y = tf32r(sm[g + 8][c]);
        o.z = tf32r(sm[g][c + 4]);
        o.w = tf32r(sm[g + 8][c + 4]);
        size_t chunk = (size_t)r16 * 128 + kblk * 16 + k8l;
        *(float4*)(g_Xa + chunk * 128 + lane * 4) = o;
    }
}

// ---------------------------------------------------------------------------
// permw_frag: w -> g_Wb (B-fragment-major permuted, tf32-rounded)
// ---------------------------------------------------------------------------
__global__ void __launch_bounds__(256)
permw_frag(const float* __restrict__ w) {
    int t = blockIdx.x * 256 + threadIdx.x;
    int lane = t & 31;
    int chunk = t >> 5;
    int k16 = chunk & 63, n8 = chunk >> 6;
    int g = lane >> 2, tg = lane & 3;
    int j2 = n8 * 8 + g;
    int j  = (j2 < 2048) ? ((j2 >> 2) * 5 + (j2 & 3)) : ((j2 - 2048) * 5 + 4);
    int k  = k16 * 16 + tg;
    float4 o;
    o.x = tf32r(w[(size_t)(k)      * NGEMM + j]);
    o.y = tf32r(w[(size_t)(k + 4)  * NGEMM + j]);
    o.z = tf32r(w[(size_t)(k + 8)  * NGEMM + j]);
    o.w = tf32r(w[(size_t)(k + 12) * NGEMM + j]);
    *(float4*)(g_Wb + (size_t)t * 4) = o;
}

// ---------------------------------------------------------------------------
// TF32 mma.sync GEMM: 128x256 CTA tile, 16 warps (4x4), warp tile 32x64.
// k8-outer ordering: same-acc reuse distance = 8 independent mmas.
// ---------------------------------------------------------------------------
__global__ void __launch_bounds__(NTHREADS, 1)
gemm_kernel(const float* __restrict__ bias) {
    extern __shared__ char smraw[];
    const uint32_t sbase = smem_u32(smraw);

    const int tid = threadIdx.x;
    const int wid = tid >> 5, lane = tid & 31;
    const int gid = lane >> 2, tig = lane & 3;
    const int wm = wid >> 2, wn = wid & 3;       // 4 x 4 warps
    const int m0 = blockIdx.y * BM;
    const int n0 = blockIdx.x * BN;

    float4 acc[2][8];        // warp tile 32 x 64: im 0..1, jn 0..7
#pragma unroll
    for (int i = 0; i < 2; i++)
#pragma unroll
        for (int j = 0; j < 8; j++) acc[i][j] = make_float4(0.f, 0.f, 0.f, 0.f);

    auto load_stage = [&](int s) {
        uint32_t sb = sbase + (uint32_t)(s & (NSTAGES - 1)) * STAGE_BYTES;
#pragma unroll
        for (int i = 0; i < 6; i++) {
            int t = i * NTHREADS + tid;           // 0..3071
            if (t < 1024) {                       // A: chunk = r16l*4 + k8l
                int chunk = t >> 5, ln = t & 31;
                int r16l = chunk >> 2, k8l = chunk & 3;
                const float* src = g_Xa +
                    ((size_t)((m0 >> 4) + r16l) * 128 + (s * 4 + k8l)) * 128 + ln * 4;
                cp_async16(sb + t * 16, src);
            } else {                              // B: chunk = n8l*2 + k16l
                int j = t - 1024;
                int chunk = j >> 5, ln = j & 31;
                int n8l = chunk >> 1, k16l = chunk & 1;
                const float* src = g_Wb +
                    ((size_t)((n0 >> 3) + n8l) * 64 + (s * 2 + k16l)) * 128 + ln * 4;
                cp_async16(sb + A_BYTES + j * 16, src);
            }
        }
        asm volatile("cp.async.commit_group;");
    };

    load_stage(0); load_stage(1); load_stage(2);

    for (int s = 0; s < KT; ++s) {
        if (s <= KT - 3)      asm volatile("cp.async.wait_group 2;");
        else if (s == KT - 2) asm volatile("cp.async.wait_group 1;");
        else                  asm volatile("cp.async.wait_group 0;");
        __syncthreads();
        if (s + 3 < KT) load_stage(s + 3);

        const char* As = smraw + (size_t)(s & (NSTAGES - 1)) * STAGE_BYTES;
        const char* Bs = As + A_BYTES;

#pragma unroll
        for (int k16 = 0; k16 < 2; k16++) {
            // A fragments: rows 16-block index = wm*2 + im ; k8 = k16*2 + q
            uint4 a[2][2];
#pragma unroll
            for (int im = 0; im < 2; im++)
#pragma unroll
                for (int q = 0; q < 2; q++)
                    a[im][q] = *(const uint4*)(As +
                        (((wm * 2 + im) * 4 + k16 * 2 + q) * 32 + lane) * 16);

#pragma unroll
            for (int jh = 0; jh < 2; jh++) {       // jn halves of 4
                uint4 b[4];
#pragma unroll
                for (int j = 0; j < 4; j++)
                    b[j] = *(const uint4*)(Bs +
                        (((wn * 8 + jh * 4 + j) * 2 + k16) * 32 + lane) * 16);
                // k8 = 0 uses (b.x,b.y); k8 = 1 uses (b.z,b.w)
#pragma unroll
                for (int j = 0; j < 4; j++)
#pragma unroll
                    for (int im = 0; im < 2; im++)
                        mma_tf32(acc[im][jh * 4 + j], a[im][0], b[j].x, b[j].y);
#pragma unroll
                for (int j = 0; j < 4; j++)
#pragma unroll
                    for (int im = 0; im < 2; im++)
                        mma_tf32(acc[im][jh * 4 + j], a[im][1], b[j].z, b[j].w);
            }
        }
    }

    // ---- epilogue: transform + float2 stores ----
#pragma unroll
    for (int im = 0; im < 2; im++) {
        const int row = m0 + wm * 32 + im * 16 + gid;
        float* r0p = g_U + (size_t)row * NGEMM;
        float* r1p = g_U + (size_t)(row + 8) * NGEMM;
#pragma unroll
        for (int jn = 0; jn < 8; jn++) {
            const int col = n0 + wn * 64 + jn * 8 + tig * 2;
            float4 c = acc[im][jn];
            if (col >= 2048) {
                float b0 = __ldg(&bias[col]);
                float b1 = __ldg(&bias[col + 1]);
                c.x = sigmoidf_fast(c.x + b0); c.y = sigmoidf_fast(c.y + b1);
                c.z = sigmoidf_fast(c.z + b0); c.w = sigmoidf_fast(c.w + b1);
            } else if (col & 2) {
                int n = col >> 2;
                float b0 = __ldg(&bias[1024 + n]);
                float b1 = __ldg(&bias[1536 + n]);
                c.x = sigmoidf_fast(c.x + b0); c.y = sigmoidf_fast(c.y + b1);
                c.z = sigmoidf_fast(c.z + b0); c.w = sigmoidf_fast(c.w + b1);
            }
            *(float2*)(r0p + col) = make_float2(c.x, c.y);
            *(float2*)(r1p + col) = make_float2(c.z, c.w);
        }
    }
}

// ---------------------------------------------------------------------------
// Scan pass 1: per-(lane, chunk) transfer coefficients.
// ---------------------------------------------------------------------------
__global__ void __launch_bounds__(256)
scan_pass1(const float* __restrict__ bias_eps) {
    int lane = blockIdx.x * 256 + threadIdx.x;   // 0..8191
    int ch   = blockIdx.y;                       // 0..15
    int n = lane & (NOUT - 1);
    int b = lane >> 9;

    float eps = sigmoidf_fast(__ldg(&bias_eps[n]));

    float a1 = 1.f, b1 = 0.f, P = 1.f, Q = 0.f, R = 0.f;

    const float4* qp = reinterpret_cast<const float4*>(g_U) +
                       (size_t)(ch * CLEN * 16 + b) * 640 + n;

#pragma unroll 4
    for (int l = 0; l < CLEN; ++l) {
        float4 q = __ldg(qp);    // (u1, u2, sig_f1, sig_f2)
        Q = fmaf(Q, q.w, a1 * q.y);
        R = fmaf(R, q.w, (eps + b1) * q.y);
        P = P * q.w;
        b1 = fmaf(b1, q.z, q.x);
        a1 = a1 * q.z;
        qp += 16 * 640;
    }
    g_coef[(ch * 5 + 0) * NLANE + lane] = a1;
    g_coef[(ch * 5 + 1) * NLANE + lane] = b1;
    g_coef[(ch * 5 + 2) * NLANE + lane] = P;
    g_coef[(ch * 5 + 3) * NLANE + lane] = Q;
    g_coef[(ch * 5 + 4) * NLANE + lane] = R;
}

// ---------------------------------------------------------------------------
// Combine: chain 16 chunks per lane; emit per-chunk initial carries + finals.
// ---------------------------------------------------------------------------
__global__ void __launch_bounds__(256)
scan_combine(float* __restrict__ out) {
    int lane = blockIdx.x * 256 + threadIdx.x;   // 0..8191
    float c1 = 0.f, c2 = 0.f;
#pragma unroll
    for (int ch = 0; ch < NCH; ++ch) {
        g_init[(ch * 2 + 0) * NLANE + lane] = c1;
        g_init[(ch * 2 + 1) * NLANE + lane] = c2;
        float a1 = g_coef[(ch * 5 + 0) * NLANE + lane];
        float b1 = g_coef[(ch * 5 + 1) * NLANE + lane];
        float P  = g_coef[(ch * 5 + 2) * NLANE + lane];
        float Q  = g_coef[(ch * 5 + 3) * NLANE + lane];
        float R  = g_coef[(ch * 5 + 4) * NLANE + lane];
        float c2n = fmaf(P, c2, fmaf(Q, c1, R));
        c1 = fmaf(a1, c1, b1);
        c2 = c2n;
    }
    const size_t GCS = (size_t)L_DIM * B_DIM * NOUT;
    out[GCS + lane]        = c1;
    out[GCS + 8192 + lane] = c2;
}

// ---------------------------------------------------------------------------
// Scan pass 2: replay each chunk from its carry; write gcs.
// ---------------------------------------------------------------------------
__global__ void __launch_bounds__(256)
scan_pass2(const float* __restrict__ bias_eps, const float* __restrict__ bias_final,
           float* __restrict__ out) {
    int lane = blockIdx.x * 256 + threadIdx.x;   // 0..8191
    int ch   = blockIdx.y;
    int n = lane & (NOUT - 1);
    int b = lane >> 9;

    float eps  = sigmoidf_fast(__ldg(&bias_eps[n]));
    float rho0 = 2.0f * sigmoidf_fast(__ldg(&bias_final[2 * n]));
    float rho1 = 2.0f * sigmoidf_fast(__ldg(&bias_final[2 * n + 1]));

    float c1 = g_init[(ch * 2 + 0) * NLANE + lane];
    float c2 = g_init[(ch * 2 + 1) * NLANE + lane];

    const float4* qp  = reinterpret_cast<const float4*>(g_U) +
                        (size_t)(ch * CLEN * 16 + b) * 640 + n;
    const float*  ogp = g_U + (size_t)(ch * CLEN * 16 + b) * 2560 + 2048 + n;
    float*        gp  = out + (size_t)ch * CLEN * NLANE + lane;

#pragma unroll 4
    for (int l = 0; l < CLEN; ++l) {
        float4 q  = __ldg(qp);
        float  og = __ldg(ogp);
        float c1n = fmaf(c1, q.z, q.x);
        float c2n = fmaf(c2, q.w, (eps + c1) * q.y);
        c1 = c1n; c2 = c2n;
        float t = og * (c1 * rho0 + c2 * rho1);
        float r;
        asm("tanh.approx.f32 %0, %1;" : "=f"(r) : "f"(t));
        *gp = r;
        qp  += 16 * 640;
        ogp += 16 * 2560;
        gp  += NLANE;
    }
}

// ---------------------------------------------------------------------------
extern "C" void kernel_launch(void* const* d_in, const int* in_sizes, int n_in,
                              void* d_out, int out_size) {
    (void)in_sizes; (void)n_in; (void)out_size;
    const float* x          = (const float*)d_in[0];
    const float* weight     = (const float*)d_in[1];
    const float* bias       = (const float*)d_in[2];
    const float* bias_eps   = (const float*)d_in[3];
    const float* bias_final = (const float*)d_in[4];
    float* out = (float*)d_out;

    cudaFuncSetAttribute(gemm_kernel, cudaFuncAttributeMaxDynamicSharedMemorySize, SMEM_DYN);

    preround_frag<<<MDIM / 16 * (KGEMM / 128), 256>>>(x);
    permw_frag<<<(NGEMM / 8) * (KGEMM / 16) * 32 / 256, 256>>>(weight);

    dim3 grid(NGEMM / BN, MDIM / BM);   // (10, 128)
    gemm_kernel<<<grid, NTHREADS, SMEM_DYN>>>(bias);

    dim3 sgrid(NLANE / 256, NCH);
    scan_pass1<<<sgrid, 256>>>(bias_eps);
    scan_combine<<<NLANE / 256, 256>>>(out);
    scan_pass2<<<sgrid, 256>>>(bias_eps, bias_final, out);
}